// round 12
// baseline (speedup 1.0000x reference)
#include <cuda_runtime.h>
#include <cuda_fp16.h>
#include <cstdint>

#define NB    65536
#define DD    64
#define NE    16
#define NO    512
#define CAP   4096
#define NPAIR 256
#define BM    128
#define BN    128
#define MAXT  1024

#define AS 136   // halves per A row (128 + 8 pad) -> 272B row stride
#define BS 136   // halves per B row

// ---- smem layout (bytes) ----
#define SM_A    0                          // 128 x 136 halves = 34816 B
#define SM_B    34816                      // 128 x 136 halves = 34816 B
#define SM_BESA 69632                      // 512 B
#define SM_BESB 70144                      // 512 B
#define SM_G    70656                      // float2[128] = 1024 B
#define SM_R    71680                      // int[128] = 512 B
#define SMEM_TOTAL 72192

// ---- scratch ----
__device__ int    g_cnt[NPAIR * 32];
__device__ int    g_rows[NPAIR * CAP];
__device__ float2 g_gates[NPAIR * CAP];
__device__ int    g_ntiles;
__device__ int4   g_tiles[MAXT];           // {pair, r0, cn, 0}
__device__ int    g_done;
__device__ __half We16[(size_t)NE * DD * NO];
// per-bucket pre-gated fp16 A rows: [g_a*x | g_b*x], 128 halves per slot (256 MB)
__device__ __half g_a16[(size_t)NPAIR * CAP * 128];

// ---- helpers ----
__device__ __forceinline__ uint32_t su32(const void* p) {
    uint32_t a;
    asm("{ .reg .u64 t; cvta.to.shared.u64 t, %1; cvt.u32.u64 %0, t; }" : "=r"(a) : "l"(p));
    return a;
}
__device__ __forceinline__ uint32_t packh2(float hi, float lo) {
    uint32_t r; asm("cvt.rn.f16x2.f32 %0, %1, %2;" : "=r"(r) : "f"(hi), "f"(lo)); return r;
}
__device__ __forceinline__ void cpa16(uint32_t dst, const void* src) {
    asm volatile("cp.async.cg.shared.global [%0], [%1], 16;" :: "r"(dst), "l"(src));
}
__device__ __forceinline__ void ldx4(uint32_t* r, uint32_t addr) {
    asm volatile("ldmatrix.sync.aligned.m8n8.x4.shared.b16 {%0,%1,%2,%3}, [%4];"
                 : "=r"(r[0]), "=r"(r[1]), "=r"(r[2]), "=r"(r[3]) : "r"(addr));
}
__device__ __forceinline__ void ldx4t(uint32_t* r, uint32_t addr) {
    asm volatile("ldmatrix.sync.aligned.m8n8.x4.trans.shared.b16 {%0,%1,%2,%3}, [%4];"
                 : "=r"(r[0]), "=r"(r[1]), "=r"(r[2]), "=r"(r[3]) : "r"(addr));
}
__device__ __forceinline__ void mma16(float* d, const uint32_t* a, uint32_t b0, uint32_t b1) {
    asm volatile(
        "mma.sync.aligned.m16n8k16.row.col.f32.f16.f16.f32 "
        "{%0,%1,%2,%3}, {%4,%5,%6,%7}, {%8,%9}, {%0,%1,%2,%3};"
        : "+f"(d[0]), "+f"(d[1]), "+f"(d[2]), "+f"(d[3])
        : "r"(a[0]), "r"(a[1]), "r"(a[2]), "r"(a[3]), "r"(b0), "r"(b1));
}

// ---------------- kernel 1: gating + conv(We) + pre-gated bucket emit + tile build ----------------
__global__ void moe_gating(const float* __restrict__ x,
                           const float* __restrict__ wg,
                           const float* __restrict__ bg,
                           const float* __restrict__ We) {
    __shared__ float wgs[DD * NE];
    __shared__ float bgs[NE];
    __shared__ int   s_last, s_total;
    int t = threadIdx.x;
    int gt = blockIdx.x * blockDim.x + t;

    // fused We -> fp16 conversion: 131072 float4 slots / 65536 threads = 2 each
    {
        const float4* W4 = (const float4*)We;
#pragma unroll
        for (int q = 0; q < 2; q++) {
            int i = gt + q * (NB);            // NB threads total
            float4 v = W4[i];
            uint2 u;
            u.x = packh2(v.y, v.x);
            u.y = packh2(v.w, v.z);
            *(uint2*)(We16 + (size_t)4 * i) = u;
        }
    }

    for (int i = t; i < DD * NE; i += blockDim.x) wgs[i] = wg[i];
    if (t < NE) bgs[t] = bg[t];
    __syncthreads();

    int row = gt;
    const float4* xr = (const float4*)(x + (size_t)row * DD);
    const float4* wgs4 = (const float4*)wgs;

    float z[NE];
#pragma unroll
    for (int e = 0; e < NE; e++) z[e] = bgs[e];
#pragma unroll
    for (int k4 = 0; k4 < DD / 4; k4++) {
        float4 xv = xr[k4];
        const float* xc = &xv.x;
#pragma unroll
        for (int kk = 0; kk < 4; kk++) {
            float xk = xc[kk];
            int kb = (k4 * 4 + kk) * 4;
            float4 w0 = wgs4[kb + 0], w1 = wgs4[kb + 1], w2 = wgs4[kb + 2], w3 = wgs4[kb + 3];
            z[0]  += xk * w0.x; z[1]  += xk * w0.y; z[2]  += xk * w0.z; z[3]  += xk * w0.w;
            z[4]  += xk * w1.x; z[5]  += xk * w1.y; z[6]  += xk * w1.z; z[7]  += xk * w1.w;
            z[8]  += xk * w2.x; z[9]  += xk * w2.y; z[10] += xk * w2.z; z[11] += xk * w2.w;
            z[12] += xk * w3.x; z[13] += xk * w3.y; z[14] += xk * w3.z; z[15] += xk * w3.w;
        }
    }

    float v0 = -1e30f, v1 = -1e30f;
    int i0 = 0, i1 = 0;
#pragma unroll
    for (int e = 0; e < NE; e++) {
        float ze = z[e];
        if (ze > v0) { v1 = v0; i1 = i0; v0 = ze; i0 = e; }
        else if (ze > v1) { v1 = ze; i1 = e; }
    }
    float s = 0.f;
#pragma unroll
    for (int e = 0; e < NE; e++) s += __expf(z[e] - v0);
    float p0 = 1.0f / s;
    float p1 = __expf(v1 - v0) / s;
    float den = p0 + p1 + 1e-6f;
    float gate0 = p0 / den, gate1 = p1 / den;

    int a, b; float ga, gb;
    if (i0 < i1) { a = i0; b = i1; ga = gate0; gb = gate1; }
    else         { a = i1; b = i0; ga = gate1; gb = gate0; }
    int p = a * NE + b;

    int pos = atomicAdd(&g_cnt[p * 32], 1);
    if (pos < CAP) {
        g_rows[p * CAP + pos]  = row;
        g_gates[p * CAP + pos] = make_float2(ga, gb);
        // emit pre-gated fp16 A row: [ga*x (64) | gb*x (64)], 256B contiguous
        __half* dst = g_a16 + ((size_t)p * CAP + pos) * 128;
#pragma unroll
        for (int q = 0; q < 8; q++) {
            float4 va = xr[2 * q], vb = xr[2 * q + 1];
            uint4 ua, ub;
            ua.x = packh2(ga * va.y, ga * va.x);
            ua.y = packh2(ga * va.w, ga * va.z);
            ua.z = packh2(ga * vb.y, ga * vb.x);
            ua.w = packh2(ga * vb.w, ga * vb.z);
            ub.x = packh2(gb * va.y, gb * va.x);
            ub.y = packh2(gb * va.w, gb * va.z);
            ub.z = packh2(gb * vb.y, gb * vb.x);
            ub.w = packh2(gb * vb.w, gb * vb.z);
            *(uint4*)(dst + 8 * q)      = ua;
            *(uint4*)(dst + 64 + 8 * q) = ub;
        }
    }

    // ---- last-block fused tile build ----
    __syncthreads();
    if (t == 0) {
        __threadfence();
        s_last = (atomicAdd(&g_done, 1) == gridDim.x - 1) ? 1 : 0;
        s_total = 0;
    }
    __syncthreads();
    if (s_last) {
        __threadfence();
        int pp = t;
        int cn = atomicAdd(&g_cnt[pp * 32], 0);
        if (cn > CAP) cn = CAP;
        int nt = (cn + BM - 1) >> 7;
        if (nt > 0) {
            int base = atomicAdd(&s_total, nt);
            for (int i = 0; i < nt; i++)
                if (base + i < MAXT) g_tiles[base + i] = make_int4(pp, i * BM, cn, 0);
        }
        g_cnt[pp * 32] = 0;
        __syncthreads();
        if (t == 0) { g_ntiles = s_total; g_done = 0; __threadfence(); }
    }
}

// ---------------- kernel 2: fp16 pair-bucket GEMM (cp.async fill + ldmatrix + mma.sync) ----------------
__global__ __launch_bounds__(256, 2)
void moe_pair_gemm(const float* __restrict__ be,
                   float* __restrict__ y) {
    int ti = blockIdx.x;
    if (ti >= g_ntiles) return;
    int4 te = g_tiles[ti];
    int p = te.x, r0 = te.y, cn = te.z;
    int ea = p >> 4, eb = p & 15;
    int o0 = blockIdx.y * BN;
    int t = threadIdx.x, wid = t >> 5, lane = t & 31;
    int wm = wid & 3, wn = wid >> 2;
    int qid = lane >> 2, qtid = lane & 3;
    int sub = lane >> 3, lr = lane & 7;

    extern __shared__ unsigned char sm[];
    uint32_t smb = su32(sm);
    float*  bA = (float*)(sm + SM_BESA);
    float*  bB = (float*)(sm + SM_BESB);
    float2* gsh = (float2*)(sm + SM_G);
    int*    rsh = (int*)(sm + SM_R);

    // ---- A fill: one contiguous 32KB block, cp.async 16B chunks ----
    {
        const __half* asrc = g_a16 + ((size_t)p * CAP + r0) * 128;
#pragma unroll
        for (int i = 0; i < 8; i++) {
            int slot = t + 256 * i;        // 0..2047 chunks of 16B
            int r = slot >> 4, c = slot & 15;
            cpa16(smb + SM_A + (uint32_t)(r * AS + c * 8) * 2, asrc + (size_t)slot * 8);
        }
    }
    // ---- B fill: row slices of We16, cp.async 16B chunks ----
    {
        const __half* Wa = We16 + ((size_t)ea * DD) * NO + o0;
        const __half* Wb = We16 + ((size_t)eb * DD) * NO + o0;
#pragma unroll
        for (int i = 0; i < 8; i++) {
            int slot = t + 256 * i;        // 0..2047
            int k = slot >> 4, c = slot & 15;
            const __half* src = ((k < 64) ? (Wa + (size_t)k * NO)
                                          : (Wb + (size_t)(k - 64) * NO)) + 8 * c;
            cpa16(smb + SM_B + (uint32_t)(k * BS + c * 8) * 2, src);
        }
    }
    asm volatile("cp.async.commit_group;" ::: "memory");

    // metadata (plain loads, overlap with cp.async)
    if (t < 128) {
        int idx = r0 + t;
        bool v = idx < cn;
        rsh[t] = v ? g_rows[p * CAP + idx] : -1;
        gsh[t] = v ? g_gates[p * CAP + idx] : make_float2(0.f, 0.f);
        bA[t] = be[(size_t)ea * NO + o0 + t];
        bB[t] = be[(size_t)eb * NO + o0 + t];
    }

    asm volatile("cp.async.wait_group 0;" ::: "memory");
    __syncthreads();

    // per-thread row metadata
    float2 G[2][2]; int R[2][2];
#pragma unroll
    for (int mt = 0; mt < 2; mt++)
#pragma unroll
        for (int j = 0; j < 2; j++) {
            int m = wm * 32 + mt * 16 + j * 8 + qid;
            G[mt][j] = gsh[m];
            R[mt][j] = rsh[m];
        }

    float acc[2][8][4];
#pragma unroll
    for (int mt = 0; mt < 2; mt++)
#pragma unroll
        for (int nt = 0; nt < 8; nt++)
#pragma unroll
            for (int c = 0; c < 4; c++) acc[mt][nt][c] = 0.f;

    // ldmatrix lane addresses
    uint32_t aadr[2], badr[4];
#pragma unroll
    for (int mt = 0; mt < 2; mt++) {
        int arow = wm * 32 + mt * 16 + (sub & 1) * 8 + lr;
        int acol = (sub >> 1) * 8;
        aadr[mt] = smb + SM_A + (uint32_t)(arow * AS + acol) * 2;
    }
#pragma unroll
    for (int pr = 0; pr < 4; pr++) {
        int brow = (sub & 1) * 8 + lr;
        int bcol = wn * 64 + pr * 16 + (sub >> 1) * 8;
        badr[pr] = smb + SM_B + (uint32_t)(brow * BS + bcol) * 2;
    }

    // main loop: 8 k16-steps
#pragma unroll
    for (int ks = 0; ks < 8; ks++) {
        uint32_t a0[4], a1[4], bb[4][4];
        ldx4(a0, aadr[0] + ks * 32);
        ldx4(a1, aadr[1] + ks * 32);
#pragma unroll
        for (int pr = 0; pr < 4; pr++) ldx4t(bb[pr], badr[pr] + ks * 16 * BS * 2);
#pragma unroll
        for (int nt = 0; nt < 8; nt++) {
            uint32_t b0 = bb[nt >> 1][(nt & 1) * 2];
            uint32_t b1 = bb[nt >> 1][(nt & 1) * 2 + 1];
            mma16(acc[0][nt], a0, b0, b1);
            mma16(acc[1][nt], a1, b0, b1);
        }
    }

    // epilogue: gated bias + one store per output element
#pragma unroll
    for (int mt = 0; mt < 2; mt++) {
#pragma unroll
        for (int j = 0; j < 2; j++) {
            int row = R[mt][j];
            if (row < 0) continue;
            float2 g = G[mt][j];
            float* yp = y + (size_t)row * NO + o0;
#pragma unroll
            for (int nt = 0; nt < 8; nt++) {
                int col = wn * 64 + nt * 8 + 2 * qtid;
                float2 ba = *(float2*)(bA + col);
                float2 bb2 = *(float2*)(bB + col);
                float2 o;
                o.x = acc[mt][nt][2 * j + 0] + g.x * ba.x + g.y * bb2.x;
                o.y = acc[mt][nt][2 * j + 1] + g.x * ba.y + g.y * bb2.y;
                *(float2*)(yp + col) = o;
            }
        }
    }
}

// ---------------- launch: exactly 2 kernels ----------------
extern "C" void kernel_launch(void* const* d_in, const int* in_sizes, int n_in,
                              void* d_out, int out_size) {
    const float* x  = (const float*)d_in[0];
    const float* wg = (const float*)d_in[1];
    const float* bg = (const float*)d_in[2];
    const float* We = (const float*)d_in[3];
    const float* be = (const float*)d_in[4];
    float* y = (float*)d_out;

    moe_gating<<<NB / 256, 256>>>(x, wg, bg, We);

    cudaFuncSetAttribute(moe_pair_gemm,
                         cudaFuncAttributeMaxDynamicSharedMemorySize, SMEM_TOTAL);
    dim3 grid(768, NO / BN, 1);
    moe_pair_gemm<<<grid, 256, SMEM_TOTAL>>>(be, y);
}